// round 1
// baseline (speedup 1.0000x reference)
#include <cuda_runtime.h>
#include <cstdint>

// ---------------------------------------------------------------------------
// Problem constants
// ---------------------------------------------------------------------------
static constexpr int H = 160, W = 288, HO = 80, WO = 144;
static constexpr int NPIX = HO * WO;     // 11520
static constexpr int DMAX = 24;          // MAXDISP / (4*S)

// ---------------------------------------------------------------------------
// Scratch (no cudaMalloc allowed) : ~60 MB of __device__ globals
// ---------------------------------------------------------------------------
__device__ float g_y_gwc[4 * 192 * NPIX];   // conv1+bn+lrelu output, gwc branch
__device__ float g_y_cat[4 * 24 * NPIX];    // conv1+bn+lrelu output, cat branch
__device__ float g_g8x[4 * 96 * NPIX];      // downsampled gwc feature
__device__ float g_c8x[4 * 12 * NPIX];      // downsampled concat feature

// ---------------------------------------------------------------------------
// conv 3x3, stride 2, pad 1, fused BN + LeakyReLU(0.1)
// Output tile per block: 8 rows x 16 cols x OCT channels.
// THREADS = 32 * (OCT/8). Thread: 4 pixels (2 rows apart) x 8 output channels.
// Input tile staged in smem, de-interleaved by column parity (sxe / sxo) so
// the stride-2 reads are bank-conflict free. Weights staged as [ic*9+k][oc]
// so each warp reads them as two broadcast LDS.128.
// ---------------------------------------------------------------------------
template<int IC, int OC, int OCT, int ICCH>
__global__ void conv3x3s2_bn_lrelu(const float* __restrict__ x,
                                   const float* __restrict__ wgt,
                                   const float* __restrict__ bg,
                                   const float* __restrict__ bb,
                                   const float* __restrict__ bm,
                                   const float* __restrict__ bv,
                                   float* __restrict__ y) {
  constexpr int NOCP = OCT / 8;
  constexpr int THREADS = 32 * NOCP;
  __shared__ float sxe[ICCH][17][24];     // even input columns (17 of them)
  __shared__ float sxo[ICCH][17][24];     // odd  input columns (16 of them)
  __shared__ float sw2[ICCH * 9][OCT];

  const int tid = threadIdx.x;
  const int qid = tid & 31;
  const int ocp = tid >> 5;
  const int tx  = qid & 15;
  const int tyh = qid >> 4;               // 0 or 1
  const int b   = blockIdx.z / (OC / OCT);
  const int ocb = blockIdx.z % (OC / OCT);
  const int ih0 = blockIdx.y * 16 - 1;
  const int iw0 = blockIdx.x * 32 - 1;

  float acc[4][8];
#pragma unroll
  for (int i = 0; i < 4; ++i)
#pragma unroll
    for (int j = 0; j < 8; ++j) acc[i][j] = 0.f;

#pragma unroll 1
  for (int icc = 0; icc < IC / ICCH; ++icc) {
    const int ic0 = icc * ICCH;
    // stage input tile (17 x 33 per channel), zero-padded at borders
    for (int i = tid; i < ICCH * 17 * 33; i += THREADS) {
      int ic  = i / 561;
      int rem = i - ic * 561;
      int r   = rem / 33;
      int c   = rem - r * 33;
      int ih = ih0 + r, iw = iw0 + c;
      float v = 0.f;
      if ((unsigned)ih < (unsigned)H && (unsigned)iw < (unsigned)W)
        v = x[((size_t)(b * IC + ic0 + ic) * H + ih) * W + iw];
      if (c & 1) sxo[ic][r][c >> 1] = v;
      else       sxe[ic][r][c >> 1] = v;
    }
    // stage weights, transposed to [ic*9+k][oc]
    for (int i = tid; i < ICCH * 9 * OCT; i += THREADS) {
      int row = i / OCT;
      int oc  = i - row * OCT;
      int ic  = row / 9;
      int kk  = row - ic * 9;
      sw2[row][oc] = wgt[((size_t)(ocb * OCT + oc) * IC + ic0 + ic) * 9 + kk];
    }
    __syncthreads();

#pragma unroll 2
    for (int ic = 0; ic < ICCH; ++ic) {
#pragma unroll
      for (int kh = 0; kh < 3; ++kh) {
#pragma unroll
        for (int kw = 0; kw < 3; ++kw) {
          const int wrow = ic * 9 + kh * 3 + kw;
          const float4 wA = *reinterpret_cast<const float4*>(&sw2[wrow][ocp * 8]);
          const float4 wB = *reinterpret_cast<const float4*>(&sw2[wrow][ocp * 8 + 4]);
#pragma unroll
          for (int i = 0; i < 4; ++i) {
            const int ty = 2 * i + tyh;
            const int r  = 2 * ty + kh;
            const float xv = (kw == 1) ? sxo[ic][r][tx]
                                       : sxe[ic][r][tx + (kw >> 1)];
            acc[i][0] += xv * wA.x; acc[i][1] += xv * wA.y;
            acc[i][2] += xv * wA.z; acc[i][3] += xv * wA.w;
            acc[i][4] += xv * wB.x; acc[i][5] += xv * wB.y;
            acc[i][6] += xv * wB.z; acc[i][7] += xv * wB.w;
          }
        }
      }
    }
    __syncthreads();
  }

  const int ow = blockIdx.x * 16 + tx;
#pragma unroll
  for (int j = 0; j < 8; ++j) {
    const int oc = ocb * OCT + ocp * 8 + j;
    const float s  = __ldg(&bg[oc]) * rsqrtf(__ldg(&bv[oc]) + 1e-5f);
    const float sh = __ldg(&bb[oc]) - __ldg(&bm[oc]) * s;
#pragma unroll
    for (int i = 0; i < 4; ++i) {
      const int oh = blockIdx.y * 8 + 2 * i + tyh;
      float v = acc[i][j] * s + sh;
      v = (v >= 0.f) ? v : 0.1f * v;
      y[((size_t)(b * OC + oc) * HO + oh) * WO + ow] = v;
    }
  }
}

// ---------------------------------------------------------------------------
// Fused: conv1x1 (CMID -> 9 logits for group g) + softmax(9) + unfold-combine.
// Block = one (batch, group); thread handles 4 consecutive pixels.
// y is NCHW so the 4-pixel read per channel is a single float4.
// Channel grouping of the downsample: channel c = cc*GR + g  (reshape C->(C/G,G)).
// ---------------------------------------------------------------------------
template<int CMID, int GR, int CIN>
__global__ void mask_combine(const float* __restrict__ y,
                             const float* __restrict__ w2,
                             const float* __restrict__ x,
                             float* __restrict__ out) {
  constexpr int CPG = CIN / GR;
  __shared__ float sw[9 * CMID];
  const int g = blockIdx.y, b = blockIdx.z;
  for (int i = threadIdx.x; i < 9 * CMID; i += 256)
    sw[i] = w2[(size_t)g * 9 * CMID + i];
  __syncthreads();

  const int p0 = (blockIdx.x * 256 + threadIdx.x) * 4;
  if (p0 >= NPIX) return;

  float lg[9][4];
#pragma unroll
  for (int k = 0; k < 9; ++k)
#pragma unroll
    for (int i = 0; i < 4; ++i) lg[k][i] = 0.f;

  const float* yb = y + (size_t)b * CMID * NPIX + p0;
#pragma unroll 4
  for (int ch = 0; ch < CMID; ++ch) {
    const float4 yv = *reinterpret_cast<const float4*>(yb + (size_t)ch * NPIX);
#pragma unroll
    for (int k = 0; k < 9; ++k) {
      const float wv = sw[k * CMID + ch];
      lg[k][0] += wv * yv.x; lg[k][1] += wv * yv.y;
      lg[k][2] += wv * yv.z; lg[k][3] += wv * yv.w;
    }
  }

  // softmax over the 9 taps, per pixel
#pragma unroll
  for (int i = 0; i < 4; ++i) {
    float m = lg[0][i];
#pragma unroll
    for (int k = 1; k < 9; ++k) m = fmaxf(m, lg[k][i]);
    float sum = 0.f;
#pragma unroll
    for (int k = 0; k < 9; ++k) { lg[k][i] = __expf(lg[k][i] - m); sum += lg[k][i]; }
    const float inv = 1.f / sum;
#pragma unroll
    for (int k = 0; k < 9; ++k) lg[k][i] *= inv;
  }

  const int oh  = p0 / WO;
  const int ow0 = p0 - oh * WO;     // p0 % 4 == 0, WO % 4 == 0 -> same row
#pragma unroll
  for (int cc = 0; cc < CPG; ++cc) {
    const int c = cc * GR + g;
    const float* xb = x + (size_t)(b * CIN + c) * H * W;
    float* ob = out + ((size_t)(b * CIN + c) * HO + oh) * WO + ow0;
#pragma unroll
    for (int i = 0; i < 4; ++i) {
      const int ow = ow0 + i;
      float s = 0.f;
#pragma unroll
      for (int kh = 0; kh < 3; ++kh) {
        const int ih = 2 * oh - 1 + kh;
        if ((unsigned)ih >= (unsigned)H) continue;
#pragma unroll
        for (int kw = 0; kw < 3; ++kw) {
          const int iw = 2 * ow - 1 + kw;
          if ((unsigned)iw >= (unsigned)W) continue;
          s += lg[kh * 3 + kw][i] * __ldg(&xb[(size_t)ih * W + iw]);
        }
      }
      ob[i] = s;
    }
  }
}

// ---------------------------------------------------------------------------
// Group-wise correlation volume. Volume grouping is the CONTIGUOUS reshape:
// group g holds channels [g*12, g*12+12). One block per (b, g, h) row.
// out[b][g][d][h][w] = (w>=d) ? mean_c l[g*12+c][h][w]*r[g*12+c][h][w-d] : 0
// ---------------------------------------------------------------------------
__global__ void gwc_volume(const float* __restrict__ g8x, float* __restrict__ out) {
  __shared__ float lrow[12][WO];
  __shared__ float rrow[12][WO];
  const int h = blockIdx.x, g = blockIdx.y, b = blockIdx.z;
  for (int i = threadIdx.x; i < 12 * WO; i += 256) {
    int c = i / WO, w = i - c * WO;
    size_t base = ((size_t)(b * 96 + g * 12 + c) * HO + h) * WO + w;
    lrow[c][w] = g8x[base];
    rrow[c][w] = g8x[base + (size_t)2 * 96 * NPIX];   // right = batch b+2
  }
  __syncthreads();
  for (int i = threadIdx.x; i < DMAX * WO; i += 256) {
    int d = i / WO, w = i - d * WO;
    float s = 0.f;
    if (w >= d) {
#pragma unroll
      for (int c = 0; c < 12; ++c) s += lrow[c][w] * rrow[c][w - d];
      s *= (1.f / 12.f);
    }
    out[(((size_t)(b * 32 + g) * DMAX + d) * HO + h) * WO + w] = s;
  }
}

// ---------------------------------------------------------------------------
// Concat volume: out channels 8..19 = left feature (w>=d ? l[w] : 0),
//                out channels 20..31 = right feature (w>=d ? r[w-d] : 0).
// ---------------------------------------------------------------------------
__global__ void cat_volume(const float* __restrict__ c8x, float* __restrict__ out) {
  const int idx = blockIdx.x * 256 + threadIdx.x;
  int w = idx % WO;
  int t = idx / WO;
  int hh = t % HO;  t /= HO;
  int d  = t % DMAX; t /= DMAX;
  int c24 = t % 24;
  int b   = t / 24;
  float v = 0.f;
  if (w >= d) {
    if (c24 < 12)
      v = c8x[((size_t)(b * 12 + c24) * HO + hh) * WO + w];
    else
      v = c8x[((size_t)((b + 2) * 12 + (c24 - 12)) * HO + hh) * WO + (w - d)];
  }
  out[(((size_t)(b * 32 + 8 + c24) * DMAX + d) * HO + hh) * WO + w] = v;
}

// ---------------------------------------------------------------------------
// launch
// ---------------------------------------------------------------------------
extern "C" void kernel_launch(void* const* d_in, const int* in_sizes, int n_in,
                              void* d_out, int out_size) {
  const float* gwc_f = (const float*)d_in[0];
  const float* cat_f = (const float*)d_in[1];
  const float* gw1 = (const float*)d_in[2];
  const float* gbg = (const float*)d_in[3];
  const float* gbb = (const float*)d_in[4];
  const float* gbm = (const float*)d_in[5];
  const float* gbv = (const float*)d_in[6];
  const float* gw2 = (const float*)d_in[7];
  const float* cw1 = (const float*)d_in[8];
  const float* cbg = (const float*)d_in[9];
  const float* cbb = (const float*)d_in[10];
  const float* cbm = (const float*)d_in[11];
  const float* cbv = (const float*)d_in[12];
  const float* cw2 = (const float*)d_in[13];
  float* out = (float*)d_out;

  float *y_gwc, *y_cat, *g8x, *c8x;
  cudaGetSymbolAddress((void**)&y_gwc, g_y_gwc);
  cudaGetSymbolAddress((void**)&y_cat, g_y_cat);
  cudaGetSymbolAddress((void**)&g8x,  g_g8x);
  cudaGetSymbolAddress((void**)&c8x,  g_c8x);

  // gwc branch: 96 -> 192, tiles 9x10, 3 oc-blocks of 64, 4 batches
  conv3x3s2_bn_lrelu<96, 192, 64, 8><<<dim3(9, 10, 12), 256>>>(
      gwc_f, gw1, gbg, gbb, gbm, gbv, y_gwc);
  // cat branch: 12 -> 24 (tiny)
  conv3x3s2_bn_lrelu<12, 24, 24, 6><<<dim3(9, 10, 4), 96>>>(
      cat_f, cw1, cbg, cbb, cbm, cbv, y_cat);

  // fused mask conv + softmax + adaptive combine
  mask_combine<192, 16, 96><<<dim3(12, 16, 4), 256>>>(y_gwc, gw2, gwc_f, g8x);
  mask_combine<24, 12, 12><<<dim3(12, 12, 4), 256>>>(y_cat, cw2, cat_f, c8x);

  // cost volumes straight into d_out
  gwc_volume<<<dim3(HO, 8, 2), 256>>>(g8x, out);
  cat_volume<<<(2 * 24 * DMAX * NPIX) / 256, 256>>>(c8x, out);
}

// round 4
// speedup vs baseline: 1.4800x; 1.4800x over previous
#include <cuda_runtime.h>
#include <cstdint>

// ---------------------------------------------------------------------------
// Problem constants
// ---------------------------------------------------------------------------
static constexpr int H = 160, W = 288, HO = 80, WO = 144;
static constexpr int NPIX = HO * WO;     // 11520
static constexpr int DMAX = 24;          // MAXDISP / (4*S)

// ---------------------------------------------------------------------------
// Scratch (__device__ globals; no cudaMalloc allowed)
// ---------------------------------------------------------------------------
__device__ float g_y_gwc[4 * 192 * NPIX];   // conv1+bn+lrelu output, gwc branch
__device__ float g_y_cat[4 * 24 * NPIX];    // conv1+bn+lrelu output, cat branch
__device__ float g_g8x[4 * 96 * NPIX];      // downsampled gwc feature
__device__ float g_c8x[4 * 12 * NPIX];      // downsampled concat feature
// packed gwc conv1 weights for mma.sync:
// layout [(chunk*9+tap)*4 + ks][oc 0..191][k4 0..3] as float2 {w(k4), w(k4+4)},
// tf32-rounded. 27*4*192*4 float2.
__device__ float2 g_wp2[27 * 4 * 192 * 4];

// ---------------------------------------------------------------------------
// helpers
// ---------------------------------------------------------------------------
__device__ __forceinline__ uint32_t cvt_tf32(float v) {
  uint32_t t; asm("cvt.rna.tf32.f32 %0, %1;" : "=r"(t) : "f"(v)); return t;
}
__device__ __forceinline__ void mma8(float* d, const uint32_t* a,
                                     uint32_t b0, uint32_t b1) {
  asm volatile(
      "mma.sync.aligned.m16n8k8.row.col.f32.tf32.tf32.f32 "
      "{%0,%1,%2,%3}, {%4,%5,%6,%7}, {%8,%9}, {%0,%1,%2,%3};"
      : "+f"(d[0]), "+f"(d[1]), "+f"(d[2]), "+f"(d[3])
      : "r"(a[0]), "r"(a[1]), "r"(a[2]), "r"(a[3]), "r"(b0), "r"(b1));
}

// ---------------------------------------------------------------------------
// Weight prep: OIHW fp32 -> packed tf32 float2 pairs for mma.sync A-fragments
// ---------------------------------------------------------------------------
__global__ void prep_weights(const float* __restrict__ w) {
  int idx = blockIdx.x * 256 + threadIdx.x;
  if (idx >= 27 * 4 * 192 * 4) return;
  int k4  = idx & 3;
  int oc  = (idx >> 2) % 192;
  int seg = idx / (192 * 4);     // tile*4 + ks
  int ks   = seg & 3;
  int tile = seg >> 2;           // chunk*9 + tap
  int chunk = tile / 9, tap = tile % 9;
  int ic_lo = chunk * 32 + ks * 8 + k4;
  float2 v;
  uint32_t lo = cvt_tf32(w[((size_t)oc * 96 + ic_lo) * 9 + tap]);
  uint32_t hi = cvt_tf32(w[((size_t)oc * 96 + ic_lo + 4) * 9 + tap]);
  v.x = __uint_as_float(lo);
  v.y = __uint_as_float(hi);
  g_wp2[idx] = v;
}

// ---------------------------------------------------------------------------
// TF32 mma.sync implicit-GEMM conv3x3 s2 p1 + BN + LeakyReLU  (96 -> 192)
// Block: 256 threads (8 warps, 2M x 4N). Tile: 64 oc x 128 px (8 rows x 16 cols).
// K = 3 ic-chunks x 9 taps x 4 k-steps(8).
// SMEM: raw input [17][32][33] floats + packed weights [9*4][64][4] float2.
// ---------------------------------------------------------------------------
static constexpr int RAW_WORDS = 17 * 32 * 33;           // 17952 floats
static constexpr int SW_OFF_B  = RAW_WORDS * 4;          // 71808
static constexpr int SW_F2     = 9 * 4 * 64 * 4;         // 9216 float2
static constexpr int SC_OFF_B  = SW_OFF_B + SW_F2 * 8;   // 145536
static constexpr int CONV_SMEM = SC_OFF_B + 2 * 64 * 4;  // 146048

__global__ __launch_bounds__(256, 1)
void conv_mma(const float* __restrict__ x,
              const float* __restrict__ bg, const float* __restrict__ bb,
              const float* __restrict__ bm, const float* __restrict__ bv,
              float* __restrict__ y) {
  extern __shared__ char smem[];
  float*  raw = (float*)smem;
  float2* sw  = (float2*)(smem + SW_OFF_B);
  float*  sc  = (float*)(smem + SC_OFF_B);
  float*  ssh = sc + 64;

  const int tid  = threadIdx.x;
  const int lane = tid & 31;
  const int wid  = tid >> 5;
  const int wm = wid >> 2;          // 0..1  (M warp row)
  const int wn = wid & 3;           // 0..3  (N warp col)
  const int lq = lane >> 2;         // 0..7
  const int lr = lane & 3;          // 0..3
  const int bx = blockIdx.x, by = blockIdx.y;
  const int b   = blockIdx.z / 3;
  const int ocb = blockIdx.z % 3;
  const int ihb = by * 16 - 1;
  const int iwb = bx * 32 - 1;

  if (tid < 64) {
    const int oc = ocb * 64 + tid;
    const float s = bg[oc] * rsqrtf(bv[oc] + 1e-5f);
    sc[tid]  = s;
    ssh[tid] = bb[oc] - bm[oc] * s;
  }

  float acc[2][4][4];
#pragma unroll
  for (int mi = 0; mi < 2; ++mi)
#pragma unroll
    for (int j = 0; j < 4; ++j)
#pragma unroll
      for (int q = 0; q < 4; ++q) acc[mi][j][q] = 0.f;

  for (int chunk = 0; chunk < 3; ++chunk) {
    __syncthreads();
    // stage raw input: raw[(ri*32+ic)*33 + ci], linear in e -> STS conflict-free
    for (int e = tid; e < 17 * 33 * 32; e += 256) {
      const int ci = e % 33;
      const int t  = e / 33;
      const int ic = t & 31;
      const int ri = t >> 5;
      const int ih = ihb + ri, iw = iwb + ci;
      float v = 0.f;
      if (ih >= 0 && iw >= 0)
        v = x[((size_t)(b * 96 + chunk * 32 + ic) * H + ih) * W + iw];
      raw[(ri * 32 + ic) * 33 + ci] = v;
    }
    // stage packed weights for this chunk (oc slice of 64)
    {
      const float2* src = g_wp2 + (size_t)chunk * 9 * 4 * 192 * 4;
      for (int e = tid; e < 9 * 4 * 256; e += 256) {
        const int seg = e >> 8;          // tap*4 + ks
        const int r   = e & 255;         // oc_local*4 + k4
        sw[seg * 256 + r] = src[(size_t)seg * 768 + ocb * 256 + r];
      }
    }
    __syncthreads();

    for (int tap = 0; tap < 9; ++tap) {
      const int kh = tap / 3, kw = tap % 3;
      int bofs[4];
#pragma unroll
      for (int j = 0; j < 4; ++j) {
        const int ri = 4 * wn + 2 * (j >> 1) + kh;
        const int ci = 16 * (j & 1) + 2 * lq + kw;
        bofs[j] = ri * (32 * 33) + ci;
      }
#pragma unroll
      for (int ks = 0; ks < 4; ++ks) {
        const float2* swb = sw + (tap * 4 + ks) * 256;
        uint32_t A[2][4];
#pragma unroll
        for (int mi = 0; mi < 2; ++mi) {
          const float2 lo = swb[(wm * 32 + mi * 16 + lq) * 4 + lr];
          const float2 hi = swb[(wm * 32 + mi * 16 + 8 + lq) * 4 + lr];
          A[mi][0] = __float_as_uint(lo.x);
          A[mi][1] = __float_as_uint(hi.x);
          A[mi][2] = __float_as_uint(lo.y);
          A[mi][3] = __float_as_uint(hi.y);
        }
#pragma unroll
        for (int j = 0; j < 4; ++j) {
          const int base = bofs[j] + (ks * 8 + lr) * 33;
          const uint32_t b0 = cvt_tf32(raw[base]);
          const uint32_t b1 = cvt_tf32(raw[base + 4 * 33]);
          mma8(acc[0][j], A[0], b0, b1);
          mma8(acc[1][j], A[1], b0, b1);
        }
      }
    }
  }

  // epilogue: BN + LeakyReLU, float2 stores into NCHW y
#pragma unroll
  for (int mi = 0; mi < 2; ++mi) {
    const int oc_l0 = wm * 32 + mi * 16 + lq;
    const int oc_l1 = oc_l0 + 8;
    const float s0 = sc[oc_l0], h0 = ssh[oc_l0];
    const float s1 = sc[oc_l1], h1 = ssh[oc_l1];
    const int oc0 = ocb * 64 + oc_l0;
#pragma unroll
    for (int j = 0; j < 4; ++j) {
      const int oh = by * 8 + wn * 2 + (j >> 1);
      const int ow = bx * 16 + (j & 1) * 8 + 2 * lr;
      float v0 = acc[mi][j][0] * s0 + h0;
      float v1 = acc[mi][j][1] * s0 + h0;
      float v2 = acc[mi][j][2] * s1 + h1;
      float v3 = acc[mi][j][3] * s1 + h1;
      v0 = (v0 >= 0.f) ? v0 : 0.1f * v0;
      v1 = (v1 >= 0.f) ? v1 : 0.1f * v1;
      v2 = (v2 >= 0.f) ? v2 : 0.1f * v2;
      v3 = (v3 >= 0.f) ? v3 : 0.1f * v3;
      float2 p0 = make_float2(v0, v1);
      float2 p1 = make_float2(v2, v3);
      *(float2*)(y + ((size_t)(b * 192 + oc0)     * HO + oh) * WO + ow) = p0;
      *(float2*)(y + ((size_t)(b * 192 + oc0 + 8) * HO + oh) * WO + ow) = p1;
    }
  }
}

// ---------------------------------------------------------------------------
// fp32 FFMA conv 3x3 s2 p1 + BN + LeakyReLU (tiny cat branch only)
// ---------------------------------------------------------------------------
template<int IC, int OC, int OCT, int ICCH>
__global__ void conv3x3s2_bn_lrelu(const float* __restrict__ x,
                                   const float* __restrict__ wgt,
                                   const float* __restrict__ bg,
                                   const float* __restrict__ bb,
                                   const float* __restrict__ bm,
                                   const float* __restrict__ bv,
                                   float* __restrict__ y) {
  constexpr int NOCP = OCT / 8;
  constexpr int THREADS = 32 * NOCP;
  __shared__ float sxe[ICCH][17][24];
  __shared__ float sxo[ICCH][17][24];
  __shared__ float sw2[ICCH * 9][OCT];

  const int tid = threadIdx.x;
  const int qid = tid & 31;
  const int ocp = tid >> 5;
  const int tx  = qid & 15;
  const int tyh = qid >> 4;
  const int b   = blockIdx.z / (OC / OCT);
  const int ocb = blockIdx.z % (OC / OCT);
  const int ih0 = blockIdx.y * 16 - 1;
  const int iw0 = blockIdx.x * 32 - 1;

  float acc[4][8];
#pragma unroll
  for (int i = 0; i < 4; ++i)
#pragma unroll
    for (int j = 0; j < 8; ++j) acc[i][j] = 0.f;

#pragma unroll 1
  for (int icc = 0; icc < IC / ICCH; ++icc) {
    const int ic0 = icc * ICCH;
    for (int i = tid; i < ICCH * 17 * 33; i += THREADS) {
      int ic  = i / 561;
      int rem = i - ic * 561;
      int r   = rem / 33;
      int c   = rem - r * 33;
      int ih = ih0 + r, iw = iw0 + c;
      float v = 0.f;
      if ((unsigned)ih < (unsigned)H && (unsigned)iw < (unsigned)W)
        v = x[((size_t)(b * IC + ic0 + ic) * H + ih) * W + iw];
      if (c & 1) sxo[ic][r][c >> 1] = v;
      else       sxe[ic][r][c >> 1] = v;
    }
    for (int i = tid; i < ICCH * 9 * OCT; i += THREADS) {
      int row = i / OCT;
      int oc  = i - row * OCT;
      int ic  = row / 9;
      int kk  = row - ic * 9;
      sw2[row][oc] = wgt[((size_t)(ocb * OCT + oc) * IC + ic0 + ic) * 9 + kk];
    }
    __syncthreads();

#pragma unroll 2
    for (int ic = 0; ic < ICCH; ++ic) {
#pragma unroll
      for (int kh = 0; kh < 3; ++kh) {
#pragma unroll
        for (int kw = 0; kw < 3; ++kw) {
          const int wrow = ic * 9 + kh * 3 + kw;
          const float4 wA = *reinterpret_cast<const float4*>(&sw2[wrow][ocp * 8]);
          const float4 wB = *reinterpret_cast<const float4*>(&sw2[wrow][ocp * 8 + 4]);
#pragma unroll
          for (int i = 0; i < 4; ++i) {
            const int ty = 2 * i + tyh;
            const int r  = 2 * ty + kh;
            const float xv = (kw == 1) ? sxo[ic][r][tx]
                                       : sxe[ic][r][tx + (kw >> 1)];
            acc[i][0] += xv * wA.x; acc[i][1] += xv * wA.y;
            acc[i][2] += xv * wA.z; acc[i][3] += xv * wA.w;
            acc[i][4] += xv * wB.x; acc[i][5] += xv * wB.y;
            acc[i][6] += xv * wB.z; acc[i][7] += xv * wB.w;
          }
        }
      }
    }
    __syncthreads();
  }

  const int ow = blockIdx.x * 16 + tx;
#pragma unroll
  for (int j = 0; j < 8; ++j) {
    const int oc = ocb * OCT + ocp * 8 + j;
    const float s  = __ldg(&bg[oc]) * rsqrtf(__ldg(&bv[oc]) + 1e-5f);
    const float sh = __ldg(&bb[oc]) - __ldg(&bm[oc]) * s;
#pragma unroll
    for (int i = 0; i < 4; ++i) {
      const int oh = blockIdx.y * 8 + 2 * i + tyh;
      float v = acc[i][j] * s + sh;
      v = (v >= 0.f) ? v : 0.1f * v;
      y[((size_t)(b * OC + oc) * HO + oh) * WO + ow] = v;
    }
  }
}

// ---------------------------------------------------------------------------
// Fused conv1x1 -> softmax(9) -> unfold-combine
// ---------------------------------------------------------------------------
template<int CMID, int GR, int CIN>
__global__ void mask_combine(const float* __restrict__ y,
                             const float* __restrict__ w2,
                             const float* __restrict__ x,
                             float* __restrict__ out) {
  constexpr int CPG = CIN / GR;
  __shared__ float sw[9 * CMID];
  const int g = blockIdx.y, b = blockIdx.z;
  for (int i = threadIdx.x; i < 9 * CMID; i += 256)
    sw[i] = w2[(size_t)g * 9 * CMID + i];
  __syncthreads();

  const int p0 = (blockIdx.x * 256 + threadIdx.x) * 4;
  if (p0 >= NPIX) return;

  float lg[9][4];
#pragma unroll
  for (int k = 0; k < 9; ++k)
#pragma unroll
    for (int i = 0; i < 4; ++i) lg[k][i] = 0.f;

  const float* yb = y + (size_t)b * CMID * NPIX + p0;
#pragma unroll 4
  for (int ch = 0; ch < CMID; ++ch) {
    const float4 yv = *reinterpret_cast<const float4*>(yb + (size_t)ch * NPIX);
#pragma unroll
    for (int k = 0; k < 9; ++k) {
      const float wv = sw[k * CMID + ch];
      lg[k][0] += wv * yv.x; lg[k][1] += wv * yv.y;
      lg[k][2] += wv * yv.z; lg[k][3] += wv * yv.w;
    }
  }

#pragma unroll
  for (int i = 0; i < 4; ++i) {
    float m = lg[0][i];
#pragma unroll
    for (int k = 1; k < 9; ++k) m = fmaxf(m, lg[k][i]);
    float sum = 0.f;
#pragma unroll
    for (int k = 0; k < 9; ++k) { lg[k][i] = __expf(lg[k][i] - m); sum += lg[k][i]; }
    const float inv = 1.f / sum;
#pragma unroll
    for (int k = 0; k < 9; ++k) lg[k][i] *= inv;
  }

  const int oh  = p0 / WO;
  const int ow0 = p0 - oh * WO;
#pragma unroll
  for (int cc = 0; cc < CPG; ++cc) {
    const int c = cc * GR + g;
    const float* xb = x + (size_t)(b * CIN + c) * H * W;
    float* ob = out + ((size_t)(b * CIN + c) * HO + oh) * WO + ow0;
#pragma unroll
    for (int i = 0; i < 4; ++i) {
      const int ow = ow0 + i;
      float s = 0.f;
#pragma unroll
      for (int kh = 0; kh < 3; ++kh) {
        const int ih = 2 * oh - 1 + kh;
        if ((unsigned)ih >= (unsigned)H) continue;
#pragma unroll
        for (int kw = 0; kw < 3; ++kw) {
          const int iw = 2 * ow - 1 + kw;
          if ((unsigned)iw >= (unsigned)W) continue;
          s += lg[kh * 3 + kw][i] * __ldg(&xb[(size_t)ih * W + iw]);
        }
      }
      ob[i] = s;
    }
  }
}

// ---------------------------------------------------------------------------
// Cost volumes
// ---------------------------------------------------------------------------
__global__ void gwc_volume(const float* __restrict__ g8x, float* __restrict__ out) {
  __shared__ float lrow[12][WO];
  __shared__ float rrow[12][WO];
  const int h = blockIdx.x, g = blockIdx.y, b = blockIdx.z;
  for (int i = threadIdx.x; i < 12 * WO; i += 256) {
    int c = i / WO, w = i - c * WO;
    size_t base = ((size_t)(b * 96 + g * 12 + c) * HO + h) * WO + w;
    lrow[c][w] = g8x[base];
    rrow[c][w] = g8x[base + (size_t)2 * 96 * NPIX];
  }
  __syncthreads();
  for (int i = threadIdx.x; i < DMAX * WO; i += 256) {
    int d = i / WO, w = i - d * WO;
    float s = 0.f;
    if (w >= d) {
#pragma unroll
      for (int c = 0; c < 12; ++c) s += lrow[c][w] * rrow[c][w - d];
      s *= (1.f / 12.f);
    }
    out[(((size_t)(b * 32 + g) * DMAX + d) * HO + h) * WO + w] = s;
  }
}

__global__ void cat_volume(const float* __restrict__ c8x, float* __restrict__ out) {
  const int idx = blockIdx.x * 256 + threadIdx.x;
  int w = idx % WO;
  int t = idx / WO;
  int hh = t % HO;  t /= HO;
  int d  = t % DMAX; t /= DMAX;
  int c24 = t % 24;
  int b   = t / 24;
  float v = 0.f;
  if (w >= d) {
    if (c24 < 12)
      v = c8x[((size_t)(b * 12 + c24) * HO + hh) * WO + w];
    else
      v = c8x[((size_t)((b + 2) * 12 + (c24 - 12)) * HO + hh) * WO + (w - d)];
  }
  out[(((size_t)(b * 32 + 8 + c24) * DMAX + d) * HO + hh) * WO + w] = v;
}

// ---------------------------------------------------------------------------
// launch
// ---------------------------------------------------------------------------
extern "C" void kernel_launch(void* const* d_in, const int* in_sizes, int n_in,
                              void* d_out, int out_size) {
  const float* gwc_f = (const float*)d_in[0];
  const float* cat_f = (const float*)d_in[1];
  const float* gw1 = (const float*)d_in[2];
  const float* gbg = (const float*)d_in[3];
  const float* gbb = (const float*)d_in[4];
  const float* gbm = (const float*)d_in[5];
  const float* gbv = (const float*)d_in[6];
  const float* gw2 = (const float*)d_in[7];
  const float* cw1 = (const float*)d_in[8];
  const float* cbg = (const float*)d_in[9];
  const float* cbb = (const float*)d_in[10];
  const float* cbm = (const float*)d_in[11];
  const float* cbv = (const float*)d_in[12];
  const float* cw2 = (const float*)d_in[13];
  float* out = (float*)d_out;

  float *y_gwc, *y_cat, *g8x, *c8x;
  cudaGetSymbolAddress((void**)&y_gwc, g_y_gwc);
  cudaGetSymbolAddress((void**)&y_cat, g_y_cat);
  cudaGetSymbolAddress((void**)&g8x,  g_g8x);
  cudaGetSymbolAddress((void**)&c8x,  g_c8x);

  cudaFuncSetAttribute(conv_mma, cudaFuncAttributeMaxDynamicSharedMemorySize,
                       CONV_SMEM);

  // pack weights for the mma conv
  prep_weights<<<(27 * 4 * 192 * 4 + 255) / 256, 256>>>(gw1);

  // gwc branch 96 -> 192 via TF32 mma.sync implicit GEMM
  conv_mma<<<dim3(9, 10, 12), 256, CONV_SMEM>>>(gwc_f, gbg, gbb, gbm, gbv, y_gwc);

  // cat branch: 12 -> 24 (tiny, FFMA)
  conv3x3s2_bn_lrelu<12, 24, 24, 6><<<dim3(9, 10, 4), 96>>>(
      cat_f, cw1, cbg, cbb, cbm, cbv, y_cat);

  // fused mask conv + softmax + adaptive combine
  mask_combine<192, 16, 96><<<dim3(12, 16, 4), 256>>>(y_gwc, gw2, gwc_f, g8x);
  mask_combine<24, 12, 12><<<dim3(12, 12, 4), 256>>>(y_cat, cw2, cat_f, c8x);

  // cost volumes straight into d_out
  gwc_volume<<<dim3(HO, 8, 2), 256>>>(g8x, out);
  cat_volume<<<(2 * 24 * DMAX * NPIX) / 256, 256>>>(c8x, out);
}

// round 6
// speedup vs baseline: 1.7299x; 1.1688x over previous
#include <cuda_runtime.h>
#include <cstdint>

// ---------------------------------------------------------------------------
// Problem constants
// ---------------------------------------------------------------------------
static constexpr int H = 160, W = 288, HO = 80, WO = 144;
static constexpr int NPIX = HO * WO;     // 11520
static constexpr int DMAX = 24;          // MAXDISP / (4*S)

// ---------------------------------------------------------------------------
// Scratch (__device__ globals; no cudaMalloc allowed)
// ---------------------------------------------------------------------------
__device__ float g_y_gwc[4 * 192 * NPIX];   // conv1+bn+lrelu output, gwc branch
__device__ float g_y_cat[4 * 24 * NPIX];    // conv1+bn+lrelu output, cat branch
__device__ float g_g8x[4 * 96 * NPIX];      // downsampled gwc feature
__device__ float g_c8x[4 * 12 * NPIX];      // downsampled concat feature
// conv1 weights as ready-made m16n8k8 A-fragments:
// [seg = (chunk*9+tap)*4+ks][mtile 0..11][lane 0..31] float4 {a0,a1,a2,a3}
__device__ float4 g_wf[108 * 12 * 32];
// mask conv2 weights as A-fragments: [kstep 0..23][mtile 0..8][lane] float4
__device__ float4 g_w2f[24 * 9 * 32];

// ---------------------------------------------------------------------------
// helpers
// ---------------------------------------------------------------------------
__device__ __forceinline__ uint32_t cvt_tf32(float v) {
  uint32_t t; asm("cvt.rna.tf32.f32 %0, %1;" : "=r"(t) : "f"(v)); return t;
}
__device__ __forceinline__ float cvt_tf32f(float v) {
  return __uint_as_float(cvt_tf32(v));
}
__device__ __forceinline__ void mma8(float* d, const uint32_t* a,
                                     uint32_t b0, uint32_t b1) {
  asm volatile(
      "mma.sync.aligned.m16n8k8.row.col.f32.tf32.tf32.f32 "
      "{%0,%1,%2,%3}, {%4,%5,%6,%7}, {%8,%9}, {%0,%1,%2,%3};"
      : "+f"(d[0]), "+f"(d[1]), "+f"(d[2]), "+f"(d[3])
      : "r"(a[0]), "r"(a[1]), "r"(a[2]), "r"(a[3]), "r"(b0), "r"(b1));
}

// ---------------------------------------------------------------------------
// Weight prep: conv1 OIHW fp32 -> fragment-major tf32 float4
// a0=W[m0+lq][ic], a1=W[m0+lq+8][ic], a2=W[m0+lq][ic+4], a3=W[m0+lq+8][ic+4]
// ---------------------------------------------------------------------------
__global__ void prep_wconv(const float* __restrict__ w) {
  int idx = blockIdx.x * 256 + threadIdx.x;
  if (idx >= 108 * 12 * 32) return;
  int lane = idx & 31;
  int mt   = (idx >> 5) % 12;
  int seg  = idx / (12 * 32);
  int ks   = seg & 3;
  int tile = seg >> 2;            // chunk*9 + tap
  int chunk = tile / 9, tap = tile % 9;
  int lq = lane >> 2, lr = lane & 3;
  int ic = chunk * 32 + ks * 8 + lr;
  int m0 = mt * 16 + lq;
  float4 f;
  f.x = cvt_tf32f(w[((size_t)m0 * 96 + ic) * 9 + tap]);
  f.y = cvt_tf32f(w[((size_t)(m0 + 8) * 96 + ic) * 9 + tap]);
  f.z = cvt_tf32f(w[((size_t)m0 * 96 + ic + 4) * 9 + tap]);
  f.w = cvt_tf32f(w[((size_t)(m0 + 8) * 96 + ic + 4) * 9 + tap]);
  g_wf[idx] = f;
}

// mask conv2 weights (144 x 192) -> fragments
__global__ void prep_w2(const float* __restrict__ w2) {
  int idx = blockIdx.x * 256 + threadIdx.x;
  if (idx >= 24 * 9 * 32) return;
  int lane = idx & 31;
  int mt   = (idx >> 5) % 9;
  int ks   = idx / (9 * 32);
  int lq = lane >> 2, lr = lane & 3;
  int k  = ks * 8 + lr;
  int m0 = mt * 16 + lq;
  float4 f;
  f.x = cvt_tf32f(w2[(size_t)m0 * 192 + k]);
  f.y = cvt_tf32f(w2[(size_t)(m0 + 8) * 192 + k]);
  f.z = cvt_tf32f(w2[(size_t)m0 * 192 + k + 4]);
  f.w = cvt_tf32f(w2[(size_t)(m0 + 8) * 192 + k + 4]);
  g_w2f[idx] = f;
}

// ---------------------------------------------------------------------------
// TF32 mma.sync implicit-GEMM conv3x3 s2 p1 + BN + LeakyReLU  (96 -> 192)
// Block: 256 threads (8 warps, 2M x 4N). Tile: 64 oc x 128 px (8 rows x 16 cols).
// A-fragments straight from L2 (g_wf). raw tile pre-converted to tf32.
// ---------------------------------------------------------------------------
static constexpr int RAW_WORDS = 17 * 32 * 33;           // 17952 floats
static constexpr int SC_OFF_B  = RAW_WORDS * 4;          // 71808
static constexpr int CONV_SMEM = SC_OFF_B + 2 * 64 * 4;  // 72320

__global__ __launch_bounds__(256, 2)
void conv_mma(const float* __restrict__ x,
              const float* __restrict__ bg, const float* __restrict__ bb,
              const float* __restrict__ bm, const float* __restrict__ bv,
              float* __restrict__ y) {
  extern __shared__ char smem[];
  float* raw = (float*)smem;
  float* sc  = (float*)(smem + SC_OFF_B);
  float* ssh = sc + 64;

  const int tid  = threadIdx.x;
  const int lane = tid & 31;
  const int wid  = tid >> 5;
  const int wm = wid >> 2;          // 0..1
  const int wn = wid & 3;           // 0..3
  const int lq = lane >> 2;         // 0..7
  const int lr = lane & 3;          // 0..3
  const int bx = blockIdx.x, by = blockIdx.y;
  const int b   = blockIdx.z / 3;
  const int ocb = blockIdx.z % 3;
  const int ihb = by * 16 - 1;
  const int iwb = bx * 32 - 1;

  if (tid < 64) {
    const int oc = ocb * 64 + tid;
    const float s = bg[oc] * rsqrtf(bv[oc] + 1e-5f);
    sc[tid]  = s;
    ssh[tid] = bb[oc] - bm[oc] * s;
  }

  float acc[2][4][4];
#pragma unroll
  for (int mi = 0; mi < 2; ++mi)
#pragma unroll
    for (int j = 0; j < 4; ++j)
#pragma unroll
      for (int q = 0; q < 4; ++q) acc[mi][j][q] = 0.f;

  for (int chunk = 0; chunk < 3; ++chunk) {
    __syncthreads();
    // stage raw input (pre-converted to tf32): raw[(ri*32+ic)*33 + ci]
    for (int e = tid; e < 17 * 33 * 32; e += 256) {
      const int ci = e % 33;
      const int t  = e / 33;
      const int ic = t & 31;
      const int ri = t >> 5;
      const int ih = ihb + ri, iw = iwb + ci;
      float v = 0.f;
      if (ih >= 0 && iw >= 0)
        v = x[((size_t)(b * 96 + chunk * 32 + ic) * H + ih) * W + iw];
      raw[(ri * 32 + ic) * 33 + ci] = cvt_tf32f(v);
    }
    __syncthreads();

    for (int tap = 0; tap < 9; ++tap) {
      const int tile = chunk * 9 + tap;
      // prefetch A fragments for all 4 k-steps x 2 m-tiles (L2-resident)
      float4 A4[4][2];
#pragma unroll
      for (int ks = 0; ks < 4; ++ks)
#pragma unroll
        for (int mi = 0; mi < 2; ++mi)
          A4[ks][mi] = __ldg(&g_wf[((size_t)(tile * 4 + ks) * 12 +
                                    ocb * 4 + wm * 2 + mi) * 32 + lane]);
      const int kh = tap / 3, kw = tap % 3;
      int bofs[4];
#pragma unroll
      for (int j = 0; j < 4; ++j) {
        const int ri = 4 * wn + 2 * (j >> 1) + kh;
        const int ci = 16 * (j & 1) + 2 * lq + kw;
        bofs[j] = ri * (32 * 33) + ci;
      }
#pragma unroll
      for (int ks = 0; ks < 4; ++ks) {
        const uint32_t* a0 = reinterpret_cast<const uint32_t*>(&A4[ks][0]);
        const uint32_t* a1 = reinterpret_cast<const uint32_t*>(&A4[ks][1]);
#pragma unroll
        for (int j = 0; j < 4; ++j) {
          const int base = bofs[j] + (ks * 8 + lr) * 33;
          const uint32_t b0 = __float_as_uint(raw[base]);
          const uint32_t b1 = __float_as_uint(raw[base + 4 * 33]);
          mma8(acc[0][j], a0, b0, b1);
          mma8(acc[1][j], a1, b0, b1);
        }
      }
    }
  }

  // epilogue: BN + LeakyReLU, float2 stores into NCHW y
#pragma unroll
  for (int mi = 0; mi < 2; ++mi) {
    const int oc_l0 = wm * 32 + mi * 16 + lq;
    const int oc_l1 = oc_l0 + 8;
    const float s0 = sc[oc_l0], h0 = ssh[oc_l0];
    const float s1 = sc[oc_l1], h1 = ssh[oc_l1];
    const int oc0 = ocb * 64 + oc_l0;
#pragma unroll
    for (int j = 0; j < 4; ++j) {
      const int oh = by * 8 + wn * 2 + (j >> 1);
      const int ow = bx * 16 + (j & 1) * 8 + 2 * lr;
      float v0 = acc[mi][j][0] * s0 + h0;
      float v1 = acc[mi][j][1] * s0 + h0;
      float v2 = acc[mi][j][2] * s1 + h1;
      float v3 = acc[mi][j][3] * s1 + h1;
      v0 = (v0 >= 0.f) ? v0 : 0.1f * v0;
      v1 = (v1 >= 0.f) ? v1 : 0.1f * v1;
      v2 = (v2 >= 0.f) ? v2 : 0.1f * v2;
      v3 = (v3 >= 0.f) ? v3 : 0.1f * v3;
      *(float2*)(y + ((size_t)(b * 192 + oc0)     * HO + oh) * WO + ow) =
          make_float2(v0, v1);
      *(float2*)(y + ((size_t)(b * 192 + oc0 + 8) * HO + oh) * WO + ow) =
          make_float2(v2, v3);
    }
  }
}

// ---------------------------------------------------------------------------
// Fused mask conv1x1 (144x192 GEMM via mma) + softmax + unfold-combine, gwc.
// One block per (h row, batch): 288 threads (9 warps, 3M x 3N).
// Phase 1: logits[144 masks][144 px] via tf32 mma, y read ONCE.
// Phase 2: raw logits -> smem; each thread softmaxes (px, g) pairs and
//          combines 6 channels of group g.
// ---------------------------------------------------------------------------
static constexpr int SY_STRIDE  = 168;                 // conflict-free b-frags
static constexpr int SL_STRIDE  = 145;
static constexpr int MASK_SMEM  = 144 * SL_STRIDE * 4; // 83520 (> sy chunk 43008)

__global__ __launch_bounds__(288, 2)
void mask_combine_mma(const float* __restrict__ y,
                      const float* __restrict__ x,
                      float* __restrict__ out) {
  extern __shared__ float smf[];
  float* sy   = smf;                      // [64][SY_STRIDE] per k-chunk
  float* slog = smf;                      // [144][SL_STRIDE] (aliases sy)

  const int tid  = threadIdx.x;
  const int lane = tid & 31;
  const int wid  = tid >> 5;              // 0..8
  const int wm = wid / 3, wn = wid % 3;
  const int lq = lane >> 2, lr = lane & 3;
  const int h = blockIdx.x, b = blockIdx.y;

  float facc[3][6][4];
#pragma unroll
  for (int mtl = 0; mtl < 3; ++mtl)
#pragma unroll
    for (int ntl = 0; ntl < 6; ++ntl)
#pragma unroll
      for (int q = 0; q < 4; ++q) facc[mtl][ntl][q] = 0.f;

  for (int kc = 0; kc < 3; ++kc) {
    __syncthreads();
    // stage y chunk [64 ch][144 px], tf32-rounded
    for (int idx = tid; idx < 64 * 144; idx += 288) {
      const int cc = idx / 144, px = idx - cc * 144;
      sy[cc * SY_STRIDE + px] =
          cvt_tf32f(y[((size_t)(b * 192 + kc * 64 + cc)) * NPIX + h * 144 + px]);
    }
    __syncthreads();

#pragma unroll
    for (int ks = 0; ks < 8; ++ks) {
      const int kseg = kc * 8 + ks;
      float4 af[3];
#pragma unroll
      for (int mtl = 0; mtl < 3; ++mtl)
        af[mtl] = __ldg(&g_w2f[((size_t)kseg * 9 + wm * 3 + mtl) * 32 + lane]);
#pragma unroll
      for (int ntl = 0; ntl < 6; ++ntl) {
        const int n0 = (wn * 6 + ntl) * 8;
        const uint32_t b0 = __float_as_uint(sy[(ks * 8 + lr) * SY_STRIDE + n0 + lq]);
        const uint32_t b1 = __float_as_uint(sy[(ks * 8 + lr + 4) * SY_STRIDE + n0 + lq]);
#pragma unroll
        for (int mtl = 0; mtl < 3; ++mtl)
          mma8(facc[mtl][ntl], reinterpret_cast<const uint32_t*>(&af[mtl]), b0, b1);
      }
    }
  }

  __syncthreads();   // done reading sy; safe to overwrite with slog
  // write raw logits to smem
#pragma unroll
  for (int mtl = 0; mtl < 3; ++mtl) {
    const int m0 = (wm * 3 + mtl) * 16;
#pragma unroll
    for (int ntl = 0; ntl < 6; ++ntl) {
      const int n0 = (wn * 6 + ntl) * 8 + 2 * lr;
      slog[(m0 + lq)     * SL_STRIDE + n0]     = facc[mtl][ntl][0];
      slog[(m0 + lq)     * SL_STRIDE + n0 + 1] = facc[mtl][ntl][1];
      slog[(m0 + lq + 8) * SL_STRIDE + n0]     = facc[mtl][ntl][2];
      slog[(m0 + lq + 8) * SL_STRIDE + n0 + 1] = facc[mtl][ntl][3];
    }
  }
  __syncthreads();

  // combine phase: thread owns px = tid%144; groups g = tid/144 + 2*i
  const int px = tid % 144;
  const int gh = tid / 144;          // 0 or 1
#pragma unroll 1
  for (int i = 0; i < 8; ++i) {
    const int g = gh + 2 * i;
    float m9[9];
#pragma unroll
    for (int k = 0; k < 9; ++k) m9[k] = slog[(g * 9 + k) * SL_STRIDE + px];
    float mx = m9[0];
#pragma unroll
    for (int k = 1; k < 9; ++k) mx = fmaxf(mx, m9[k]);
    float sum = 0.f;
#pragma unroll
    for (int k = 0; k < 9; ++k) { m9[k] = __expf(m9[k] - mx); sum += m9[k]; }
    const float inv = 1.f / sum;
#pragma unroll
    for (int k = 0; k < 9; ++k) m9[k] *= inv;

#pragma unroll 1
    for (int cc = 0; cc < 6; ++cc) {
      const int c = cc * 16 + g;
      const float* xb = x + (size_t)(b * 96 + c) * H * W;
      float s = 0.f;
#pragma unroll
      for (int kh = 0; kh < 3; ++kh) {
        const int ih = 2 * h - 1 + kh;
        if ((unsigned)ih >= (unsigned)H) continue;
#pragma unroll
        for (int kw = 0; kw < 3; ++kw) {
          const int iw = 2 * px - 1 + kw;
          if ((unsigned)iw >= (unsigned)W) continue;
          s += m9[kh * 3 + kw] * __ldg(&xb[(size_t)ih * W + iw]);
        }
      }
      out[(size_t)(b * 96 + c) * NPIX + h * 144 + px] = s;
    }
  }
}

// ---------------------------------------------------------------------------
// fp32 FFMA conv 3x3 s2 p1 + BN + LeakyReLU (tiny cat branch only)
// ---------------------------------------------------------------------------
template<int IC, int OC, int OCT, int ICCH>
__global__ void conv3x3s2_bn_lrelu(const float* __restrict__ x,
                                   const float* __restrict__ wgt,
                                   const float* __restrict__ bg,
                                   const float* __restrict__ bb,
                                   const float* __restrict__ bm,
                                   const float* __restrict__ bv,
                                   float* __restrict__ y) {
  constexpr int NOCP = OCT / 8;
  constexpr int THREADS = 32 * NOCP;
  __shared__ float sxe[ICCH][17][24];
  __shared__ float sxo[ICCH][17][24];
  __shared__ float sw2[ICCH * 9][OCT];

  const int tid = threadIdx.x;
  const int qid = tid & 31;
  const int ocp = tid >> 5;
  const int tx  = qid & 15;
  const int tyh = qid >> 4;
  const int b   = blockIdx.z / (OC / OCT);
  const int ocb = blockIdx.z % (OC / OCT);
  const int ih0 = blockIdx.y * 16 - 1;
  const int iw0 = blockIdx.x * 32 - 1;

  float acc[4][8];
#pragma unroll
  for (int i = 0; i < 4; ++i)
#pragma unroll
    for (int j = 0; j < 8; ++j) acc[i][j] = 0.f;

#pragma unroll 1
  for (int icc = 0; icc < IC / ICCH; ++icc) {
    const int ic0 = icc * ICCH;
    for (int i = tid; i < ICCH * 17 * 33; i += THREADS) {
      int ic  = i / 561;
      int rem = i - ic * 561;
      int r   = rem / 33;
      int c   = rem - r * 33;
      int ih = ih0 + r, iw = iw0 + c;
      float v = 0.f;
      if ((unsigned)ih < (unsigned)H && (unsigned)iw < (unsigned)W)
        v = x[((size_t)(b * IC + ic0 + ic) * H + ih) * W + iw];
      if (c & 1) sxo[ic][r][c >> 1] = v;
      else       sxe[ic][r][c >> 1] = v;
    }
    for (int i = tid; i < ICCH * 9 * OCT; i += THREADS) {
      int row = i / OCT;
      int oc  = i - row * OCT;
      int ic  = row / 9;
      int kk  = row - ic * 9;
      sw2[row][oc] = wgt[((size_t)(ocb * OCT + oc) * IC + ic0 + ic) * 9 + kk];
    }
    __syncthreads();

#pragma unroll 2
    for (int ic = 0; ic < ICCH; ++ic) {
#pragma unroll
      for (int kh = 0; kh < 3; ++kh) {
#pragma unroll
        for (int kw = 0; kw < 3; ++kw) {
          const int wrow = ic * 9 + kh * 3 + kw;
          const float4 wA = *reinterpret_cast<const float4*>(&sw2[wrow][ocp * 8]);
          const float4 wB = *reinterpret_cast<const float4*>(&sw2[wrow][ocp * 8 + 4]);
#pragma unroll
          for (int i = 0; i < 4; ++i) {
            const int ty = 2 * i + tyh;
            const int r  = 2 * ty + kh;
            const float xv = (kw == 1) ? sxo[ic][r][tx]
                                       : sxe[ic][r][tx + (kw >> 1)];
            acc[i][0] += xv * wA.x; acc[i][1] += xv * wA.y;
            acc[i][2] += xv * wA.z; acc[i][3] += xv * wA.w;
            acc[i][4] += xv * wB.x; acc[i][5] += xv * wB.y;
            acc[i][6] += xv * wB.z; acc[i][7] += xv * wB.w;
          }
        }
      }
    }
    __syncthreads();
  }

  const int ow = blockIdx.x * 16 + tx;
#pragma unroll
  for (int j = 0; j < 8; ++j) {
    const int oc = ocb * OCT + ocp * 8 + j;
    const float s  = __ldg(&bg[oc]) * rsqrtf(__ldg(&bv[oc]) + 1e-5f);
    const float sh = __ldg(&bb[oc]) - __ldg(&bm[oc]) * s;
#pragma unroll
    for (int i = 0; i < 4; ++i) {
      const int oh = blockIdx.y * 8 + 2 * i + tyh;
      float v = acc[i][j] * s + sh;
      v = (v >= 0.f) ? v : 0.1f * v;
      y[((size_t)(b * OC + oc) * HO + oh) * WO + ow] = v;
    }
  }
}

// ---------------------------------------------------------------------------
// Fused conv1x1 -> softmax(9) -> unfold-combine (FFMA; cat branch only)
// ---------------------------------------------------------------------------
template<int CMID, int GR, int CIN>
__global__ void mask_combine(const float* __restrict__ y,
                             const float* __restrict__ w2,
                             const float* __restrict__ x,
                             float* __restrict__ out) {
  constexpr int CPG = CIN / GR;
  __shared__ float sw[9 * CMID];
  const int g = blockIdx.y, b = blockIdx.z;
  for (int i = threadIdx.x; i < 9 * CMID; i += 256)
    sw[i] = w2[(size_t)g * 9 * CMID + i];
  __syncthreads();

  const int p0 = (blockIdx.x * 256 + threadIdx.x) * 4;
  if (p0 >= NPIX) return;

  float lg[9][4];
#pragma unroll
  for (int k = 0; k < 9; ++k)
#pragma unroll
    for (int i = 0; i < 4; ++i) lg[k][i] = 0.f;

  const float* yb = y + (size_t)b * CMID * NPIX + p0;
#pragma unroll 4
  for (int ch = 0; ch < CMID; ++ch) {
    const float4 yv = *reinterpret_cast<const float4*>(yb + (size_t)ch * NPIX);
#pragma unroll
    for (int k = 0; k < 9; ++k) {
      const float wv = sw[k * CMID + ch];
      lg[k][0] += wv * yv.x; lg[k][1] += wv * yv.y;
      lg[k][2] += wv * yv.z; lg[k][3] += wv * yv.w;
    }
  }

#pragma unroll
  for (int i = 0; i < 4; ++i) {
    float m = lg[0][i];
#pragma unroll
    for (int k = 1; k < 9; ++k) m = fmaxf(m, lg[k][i]);
    float sum = 0.f;
#pragma unroll
    for (int k = 0; k < 9; ++k) { lg[k][i] = __expf(lg[k][i] - m); sum += lg[k][i]; }
    const float inv = 1.f / sum;
#pragma unroll
    for (int k = 0; k < 9; ++k) lg[k][i] *= inv;
  }

  const int oh  = p0 / WO;
  const int ow0 = p0 - oh * WO;
#pragma unroll
  for (int cc = 0; cc < CPG; ++cc) {
    const int c = cc * GR + g;
    const float* xb = x + (size_t)(b * CIN + c) * H * W;
    float* ob = out + ((size_t)(b * CIN + c) * HO + oh) * WO + ow0;
#pragma unroll
    for (int i = 0; i < 4; ++i) {
      const int ow = ow0 + i;
      float s = 0.f;
#pragma unroll
      for (int kh = 0; kh < 3; ++kh) {
        const int ih = 2 * oh - 1 + kh;
        if ((unsigned)ih >= (unsigned)H) continue;
#pragma unroll
        for (int kw = 0; kw < 3; ++kw) {
          const int iw = 2 * ow - 1 + kw;
          if ((unsigned)iw >= (unsigned)W) continue;
          s += lg[kh * 3 + kw][i] * __ldg(&xb[(size_t)ih * W + iw]);
        }
      }
      ob[i] = s;
    }
  }
}

// ---------------------------------------------------------------------------
// Cost volumes
// ---------------------------------------------------------------------------
__global__ void gwc_volume(const float* __restrict__ g8x, float* __restrict__ out) {
  __shared__ float lrow[12][WO];
  __shared__ float rrow[12][WO];
  const int h = blockIdx.x, g = blockIdx.y, b = blockIdx.z;
  for (int i = threadIdx.x; i < 12 * WO; i += 256) {
    int c = i / WO, w = i - c * WO;
    size_t base = ((size_t)(b * 96 + g * 12 + c) * HO + h) * WO + w;
    lrow[c][w] = g8x[base];
    rrow[c][w] = g8x[base + (size_t)2 * 96 * NPIX];
  }
  __syncthreads();
  for (int i = threadIdx.x; i < DMAX * WO; i += 256) {
    int d = i / WO, w = i - d * WO;
    float s = 0.f;
    if (w >= d) {
#pragma unroll
      for (int c = 0; c < 12; ++c) s += lrow[c][w] * rrow[c][w - d];
      s *= (1.f / 12.f);
    }
    out[(((size_t)(b * 32 + g) * DMAX + d) * HO + h) * WO + w] = s;
  }
}

__global__ void cat_volume(const float* __restrict__ c8x, float* __restrict__ out) {
  const int idx = blockIdx.x * 256 + threadIdx.x;
  int w = idx % WO;
  int t = idx / WO;
  int hh = t % HO;  t /= HO;
  int d  = t % DMAX; t /= DMAX;
  int c24 = t % 24;
  int b   = t / 24;
  float v = 0.f;
  if (w >= d) {
    if (c24 < 12)
      v = c8x[((size_t)(b * 12 + c24) * HO + hh) * WO + w];
    else
      v = c8x[((size_t)((b + 2) * 12 + (c24 - 12)) * HO + hh) * WO + (w - d)];
  }
  out[(((size_t)(b * 32 + 8 + c24) * DMAX + d) * HO + hh) * WO + w] = v;
}

// ---------------------------------------------------------------------------
// launch
// ---------------------------------------------------------------------------
extern "C" void kernel_launch(void* const* d_in, const int* in_sizes, int n_in,
                              void* d_out, int out_size) {
  const float* gwc_f = (const float*)d_in[0];
  const float* cat_f = (const float*)d_in[1];
  const float* gw1 = (const float*)d_in[2];
  const float* gbg = (const float*)d_in[3];
  const float* gbb = (const float*)d_in[4];
  const float* gbm = (const float*)d_in[5];
  const float* gbv = (const float*)d_in[6];
  const float* gw2 = (const float*)d_in[7];
  const float* cw1 = (const float*)d_in[8];
  const float* cbg = (const float*)d_in[9];
  const float* cbb = (const float*)d_in[10];
  const float* cbm = (const float*)d_in[11];
  const float* cbv = (const float*)d_in[12];
  const float* cw2 = (const float*)d_in[13];
  float* out = (float*)d_out;

  float *y_gwc, *y_cat, *g8x, *c8x;
  cudaGetSymbolAddress((void**)&y_gwc, g_y_gwc);
  cudaGetSymbolAddress((void**)&y_cat, g_y_cat);
  cudaGetSymbolAddress((void**)&g8x,  g_g8x);
  cudaGetSymbolAddress((void**)&c8x,  g_c8x);

  cudaFuncSetAttribute(conv_mma, cudaFuncAttributeMaxDynamicSharedMemorySize,
                       CONV_SMEM);
  cudaFuncSetAttribute(mask_combine_mma,
                       cudaFuncAttributeMaxDynamicSharedMemorySize, MASK_SMEM);

  // weight prep
  prep_wconv<<<(108 * 12 * 32 + 255) / 256, 256>>>(gw1);
  prep_w2<<<(24 * 9 * 32 + 255) / 256, 256>>>(gw2);

  // gwc branch 96 -> 192 via TF32 mma.sync implicit GEMM
  conv_mma<<<dim3(9, 10, 12), 256, CONV_SMEM>>>(gwc_f, gbg, gbb, gbm, gbv, y_gwc);

  // cat branch: 12 -> 24 (tiny, FFMA)
  conv3x3s2_bn_lrelu<12, 24, 24, 6><<<dim3(9, 10, 4), 96>>>(
      cat_f, cw1, cbg, cbb, cbm, cbv, y_cat);

  // fused mask conv (mma) + softmax + adaptive combine, gwc branch
  mask_combine_mma<<<dim3(80, 4), 288, MASK_SMEM>>>(y_gwc, gwc_f, g8x);
  // cat branch mask+combine (FFMA)
  mask_combine<24, 12, 12><<<dim3(12, 12, 4), 256>>>(y_cat, cw2, cat_f, c8x);

  // cost volumes straight into d_out
  gwc_volume<<<dim3(HO, 8, 2), 256>>>(g8x, out);
  cat_volume<<<(2 * 24 * DMAX * NPIX) / 256, 256>>>(c8x, out);
}

// round 7
// speedup vs baseline: 1.7505x; 1.0119x over previous
#include <cuda_runtime.h>
#include <cstdint>

// ---------------------------------------------------------------------------
// Problem constants
// ---------------------------------------------------------------------------
static constexpr int H = 160, W = 288, HO = 80, WO = 144;
static constexpr int NPIX = HO * WO;     // 11520
static constexpr int DMAX = 24;          // MAXDISP / (4*S)

// ---------------------------------------------------------------------------
// Scratch (__device__ globals; no cudaMalloc allowed)
// ---------------------------------------------------------------------------
__device__ float g_y_gwc[4 * 192 * NPIX];   // conv1+bn+lrelu output, gwc branch
__device__ float g_g8x[4 * 96 * NPIX];      // downsampled gwc feature
__device__ float g_c8x[4 * 12 * NPIX];      // downsampled concat feature
// conv1 weights as ready-made m16n8k8 A-fragments:
// [seg = (chunk*9+tap)*4+ks][mtile 0..11][lane 0..31] float4 {a0,a1,a2,a3}
__device__ float4 g_wf[108 * 12 * 32];
// mask conv2 weights as A-fragments: [kstep 0..23][mtile 0..8][lane] float4
__device__ float4 g_w2f[24 * 9 * 32];

// ---------------------------------------------------------------------------
// helpers
// ---------------------------------------------------------------------------
__device__ __forceinline__ uint32_t cvt_tf32(float v) {
  uint32_t t; asm("cvt.rna.tf32.f32 %0, %1;" : "=r"(t) : "f"(v)); return t;
}
__device__ __forceinline__ float cvt_tf32f(float v) {
  return __uint_as_float(cvt_tf32(v));
}
__device__ __forceinline__ void mma8(float* d, const uint32_t* a,
                                     uint32_t b0, uint32_t b1) {
  asm volatile(
      "mma.sync.aligned.m16n8k8.row.col.f32.tf32.tf32.f32 "
      "{%0,%1,%2,%3}, {%4,%5,%6,%7}, {%8,%9}, {%0,%1,%2,%3};"
      : "+f"(d[0]), "+f"(d[1]), "+f"(d[2]), "+f"(d[3])
      : "r"(a[0]), "r"(a[1]), "r"(a[2]), "r"(a[3]), "r"(b0), "r"(b1));
}

// ---------------------------------------------------------------------------
// Weight prep (single launch): conv1 + mask-conv2 fragments, tf32 float4
// ---------------------------------------------------------------------------
__global__ void prep_all(const float* __restrict__ w, const float* __restrict__ w2) {
  int idx = blockIdx.x * 256 + threadIdx.x;
  if (idx < 108 * 12 * 32) {
    int lane = idx & 31;
    int mt   = (idx >> 5) % 12;
    int seg  = idx / (12 * 32);
    int ks   = seg & 3;
    int tile = seg >> 2;            // chunk*9 + tap
    int chunk = tile / 9, tap = tile % 9;
    int lq = lane >> 2, lr = lane & 3;
    int ic = chunk * 32 + ks * 8 + lr;
    int m0 = mt * 16 + lq;
    float4 f;
    f.x = cvt_tf32f(w[((size_t)m0 * 96 + ic) * 9 + tap]);
    f.y = cvt_tf32f(w[((size_t)(m0 + 8) * 96 + ic) * 9 + tap]);
    f.z = cvt_tf32f(w[((size_t)m0 * 96 + ic + 4) * 9 + tap]);
    f.w = cvt_tf32f(w[((size_t)(m0 + 8) * 96 + ic + 4) * 9 + tap]);
    g_wf[idx] = f;
  } else {
    int j = idx - 108 * 12 * 32;
    if (j >= 24 * 9 * 32) return;
    int lane = j & 31;
    int mt   = (j >> 5) % 9;
    int ks   = j / (9 * 32);
    int lq = lane >> 2, lr = lane & 3;
    int k  = ks * 8 + lr;
    int m0 = mt * 16 + lq;
    float4 f;
    f.x = cvt_tf32f(w2[(size_t)m0 * 192 + k]);
    f.y = cvt_tf32f(w2[(size_t)(m0 + 8) * 192 + k]);
    f.z = cvt_tf32f(w2[(size_t)m0 * 192 + k + 4]);
    f.w = cvt_tf32f(w2[(size_t)(m0 + 8) * 192 + k + 4]);
    g_w2f[j] = f;
  }
}

// ---------------------------------------------------------------------------
// TF32 mma.sync implicit-GEMM conv3x3 s2 p1 + BN + LeakyReLU  (96 -> 192)
// Block: 256 threads (8 warps, 2M x 4N). Tile: 64 oc x 128 px (8 rows x 16 cols).
// A-fragments straight from L2 (g_wf). raw tile pre-converted to tf32.
// ---------------------------------------------------------------------------
static constexpr int RAW_WORDS = 17 * 32 * 33;           // 17952 floats
static constexpr int SC_OFF_B  = RAW_WORDS * 4;          // 71808
static constexpr int CONV_SMEM = SC_OFF_B + 2 * 64 * 4;  // 72320

__global__ __launch_bounds__(256, 2)
void conv_mma(const float* __restrict__ x,
              const float* __restrict__ bg, const float* __restrict__ bb,
              const float* __restrict__ bm, const float* __restrict__ bv,
              float* __restrict__ y) {
  extern __shared__ char smem[];
  float* raw = (float*)smem;
  float* sc  = (float*)(smem + SC_OFF_B);
  float* ssh = sc + 64;

  const int tid  = threadIdx.x;
  const int lane = tid & 31;
  const int wid  = tid >> 5;
  const int wm = wid >> 2;          // 0..1
  const int wn = wid & 3;           // 0..3
  const int lq = lane >> 2;         // 0..7
  const int lr = lane & 3;          // 0..3
  const int bx = blockIdx.x, by = blockIdx.y;
  const int b   = blockIdx.z / 3;
  const int ocb = blockIdx.z % 3;
  const int ihb = by * 16 - 1;
  const int iwb = bx * 32 - 1;

  if (tid < 64) {
    const int oc = ocb * 64 + tid;
    const float s = bg[oc] * rsqrtf(bv[oc] + 1e-5f);
    sc[tid]  = s;
    ssh[tid] = bb[oc] - bm[oc] * s;
  }

  float acc[2][4][4];
#pragma unroll
  for (int mi = 0; mi < 2; ++mi)
#pragma unroll
    for (int j = 0; j < 4; ++j)
#pragma unroll
      for (int q = 0; q < 4; ++q) acc[mi][j][q] = 0.f;

  for (int chunk = 0; chunk < 3; ++chunk) {
    __syncthreads();
    // stage raw input (pre-converted to tf32): raw[(ri*32+ic)*33 + ci]
    for (int e = tid; e < 17 * 33 * 32; e += 256) {
      const int ci = e % 33;
      const int t  = e / 33;
      const int ic = t & 31;
      const int ri = t >> 5;
      const int ih = ihb + ri, iw = iwb + ci;
      float v = 0.f;
      if (ih >= 0 && iw >= 0)
        v = x[((size_t)(b * 96 + chunk * 32 + ic) * H + ih) * W + iw];
      raw[(ri * 32 + ic) * 33 + ci] = cvt_tf32f(v);
    }
    __syncthreads();

    for (int tap = 0; tap < 9; ++tap) {
      const int tile = chunk * 9 + tap;
      // prefetch A fragments for all 4 k-steps x 2 m-tiles (L2-resident)
      float4 A4[4][2];
#pragma unroll
      for (int ks = 0; ks < 4; ++ks)
#pragma unroll
        for (int mi = 0; mi < 2; ++mi)
          A4[ks][mi] = __ldg(&g_wf[((size_t)(tile * 4 + ks) * 12 +
                                    ocb * 4 + wm * 2 + mi) * 32 + lane]);
      const int kh = tap / 3, kw = tap % 3;
      int bofs[4];
#pragma unroll
      for (int j = 0; j < 4; ++j) {
        const int ri = 4 * wn + 2 * (j >> 1) + kh;
        const int ci = 16 * (j & 1) + 2 * lq + kw;
        bofs[j] = ri * (32 * 33) + ci;
      }
#pragma unroll
      for (int ks = 0; ks < 4; ++ks) {
        const uint32_t* a0 = reinterpret_cast<const uint32_t*>(&A4[ks][0]);
        const uint32_t* a1 = reinterpret_cast<const uint32_t*>(&A4[ks][1]);
#pragma unroll
        for (int j = 0; j < 4; ++j) {
          const int base = bofs[j] + (ks * 8 + lr) * 33;
          const uint32_t b0 = __float_as_uint(raw[base]);
          const uint32_t b1 = __float_as_uint(raw[base + 4 * 33]);
          mma8(acc[0][j], a0, b0, b1);
          mma8(acc[1][j], a1, b0, b1);
        }
      }
    }
  }

  // epilogue: BN + LeakyReLU, float2 stores into NCHW y
#pragma unroll
  for (int mi = 0; mi < 2; ++mi) {
    const int oc_l0 = wm * 32 + mi * 16 + lq;
    const int oc_l1 = oc_l0 + 8;
    const float s0 = sc[oc_l0], h0 = ssh[oc_l0];
    const float s1 = sc[oc_l1], h1 = ssh[oc_l1];
    const int oc0 = ocb * 64 + oc_l0;
#pragma unroll
    for (int j = 0; j < 4; ++j) {
      const int oh = by * 8 + wn * 2 + (j >> 1);
      const int ow = bx * 16 + (j & 1) * 8 + 2 * lr;
      float v0 = acc[mi][j][0] * s0 + h0;
      float v1 = acc[mi][j][1] * s0 + h0;
      float v2 = acc[mi][j][2] * s1 + h1;
      float v3 = acc[mi][j][3] * s1 + h1;
      v0 = (v0 >= 0.f) ? v0 : 0.1f * v0;
      v1 = (v1 >= 0.f) ? v1 : 0.1f * v1;
      v2 = (v2 >= 0.f) ? v2 : 0.1f * v2;
      v3 = (v3 >= 0.f) ? v3 : 0.1f * v3;
      *(float2*)(y + ((size_t)(b * 192 + oc0)     * HO + oh) * WO + ow) =
          make_float2(v0, v1);
      *(float2*)(y + ((size_t)(b * 192 + oc0 + 8) * HO + oh) * WO + ow) =
          make_float2(v2, v3);
    }
  }
}

// ---------------------------------------------------------------------------
// Fused mask conv1x1 (144x192 GEMM via mma) + softmax + unfold-combine, gwc.
// One block per (h row, batch): 288 threads (9 warps, 3M x 3N).
// ---------------------------------------------------------------------------
static constexpr int SY_STRIDE  = 168;                 // conflict-free b-frags
static constexpr int SL_STRIDE  = 145;
static constexpr int MASK_SMEM  = 144 * SL_STRIDE * 4; // 83520 (> sy chunk 43008)

__global__ __launch_bounds__(288, 2)
void mask_combine_mma(const float* __restrict__ y,
                      const float* __restrict__ x,
                      float* __restrict__ out) {
  extern __shared__ float smf[];
  float* sy   = smf;                      // [64][SY_STRIDE] per k-chunk
  float* slog = smf;                      // [144][SL_STRIDE] (aliases sy)

  const int tid  = threadIdx.x;
  const int lane = tid & 31;
  const int wid  = tid >> 5;              // 0..8
  const int wm = wid / 3, wn = wid % 3;
  const int lq = lane >> 2, lr = lane & 3;
  const int h = blockIdx.x, b = blockIdx.y;

  float facc[3][6][4];
#pragma unroll
  for (int mtl = 0; mtl < 3; ++mtl)
#pragma unroll
    for (int ntl = 0; ntl < 6; ++ntl)
#pragma unroll
      for (int q = 0; q < 4; ++q) facc[mtl][ntl][q] = 0.f;

  for (int kc = 0; kc < 3; ++kc) {
    __syncthreads();
    // stage y chunk [64 ch][144 px], tf32-rounded
    for (int idx = tid; idx < 64 * 144; idx += 288) {
      const int cc = idx / 144, px = idx - cc * 144;
      sy[cc * SY_STRIDE + px] =
          cvt_tf32f(y[((size_t)(b * 192 + kc * 64 + cc)) * NPIX + h * 144 + px]);
    }
    __syncthreads();

#pragma unroll
    for (int ks = 0; ks < 8; ++ks) {
      const int kseg = kc * 8 + ks;
      float4 af[3];
#pragma unroll
      for (int mtl = 0; mtl < 3; ++mtl)
        af[mtl] = __ldg(&g_w2f[((size_t)kseg * 9 + wm * 3 + mtl) * 32 + lane]);
#pragma unroll
      for (int ntl = 0; ntl < 6; ++ntl) {
        const int n0 = (wn * 6 + ntl) * 8;
        const uint32_t b0 = __float_as_uint(sy[(ks * 8 + lr) * SY_STRIDE + n0 + lq]);
        const uint32_t b1 = __float_as_uint(sy[(ks * 8 + lr + 4) * SY_STRIDE + n0 + lq]);
#pragma unroll
        for (int mtl = 0; mtl < 3; ++mtl)
          mma8(facc[mtl][ntl], reinterpret_cast<const uint32_t*>(&af[mtl]), b0, b1);
      }
    }
  }

  __syncthreads();   // done reading sy; safe to overwrite with slog
  // write raw logits to smem
#pragma unroll
  for (int mtl = 0; mtl < 3; ++mtl) {
    const int m0 = (wm * 3 + mtl) * 16;
#pragma unroll
    for (int ntl = 0; ntl < 6; ++ntl) {
      const int n0 = (wn * 6 + ntl) * 8 + 2 * lr;
      slog[(m0 + lq)     * SL_STRIDE + n0]     = facc[mtl][ntl][0];
      slog[(m0 + lq)     * SL_STRIDE + n0 + 1] = facc[mtl][ntl][1];
      slog[(m0 + lq + 8) * SL_STRIDE + n0]     = facc[mtl][ntl][2];
      slog[(m0 + lq + 8) * SL_STRIDE + n0 + 1] = facc[mtl][ntl][3];
    }
  }
  __syncthreads();

  // combine phase: thread owns px = tid%144; groups g = tid/144 + 2*i
  const int px = tid % 144;
  const int gh = tid / 144;          // 0 or 1
#pragma unroll 1
  for (int i = 0; i < 8; ++i) {
    const int g = gh + 2 * i;
    float m9[9];
#pragma unroll
    for (int k = 0; k < 9; ++k) m9[k] = slog[(g * 9 + k) * SL_STRIDE + px];
    float mx = m9[0];
#pragma unroll
    for (int k = 1; k < 9; ++k) mx = fmaxf(mx, m9[k]);
    float sum = 0.f;
#pragma unroll
    for (int k = 0; k < 9; ++k) { m9[k] = __expf(m9[k] - mx); sum += m9[k]; }
    const float inv = 1.f / sum;
#pragma unroll
    for (int k = 0; k < 9; ++k) m9[k] *= inv;

#pragma unroll 1
    for (int cc = 0; cc < 6; ++cc) {
      const int c = cc * 16 + g;
      const float* xb = x + (size_t)(b * 96 + c) * H * W;
      float s = 0.f;
#pragma unroll
      for (int kh = 0; kh < 3; ++kh) {
        const int ih = 2 * h - 1 + kh;
        if ((unsigned)ih >= (unsigned)H) continue;
#pragma unroll
        for (int kw = 0; kw < 3; ++kw) {
          const int iw = 2 * px - 1 + kw;
          if ((unsigned)iw >= (unsigned)W) continue;
          s += m9[kh * 3 + kw] * __ldg(&xb[(size_t)ih * W + iw]);
        }
      }
      out[(size_t)(b * 96 + c) * NPIX + h * 144 + px] = s;
    }
  }
}

// ---------------------------------------------------------------------------
// Fully fused cat branch: conv3x3 s2 (12->24) + BN + LeakyReLU + mask conv1x1
// (24->108) + softmax(9) + unfold-combine, one block per (b, output row).
// 288 threads: thread = (px 0..143, half 0..1). Zero-padded x staging makes
// all boundary handling implicit (matches reference zero-pad unfold).
// ---------------------------------------------------------------------------
static constexpr int CF_SX   = 0;                       // [3][12][292] floats
static constexpr int CF_SY   = 3 * 12 * 292;            // 10512 -> [24][148]
static constexpr int CF_SW1  = CF_SY + 24 * 148;        // [108][24]
static constexpr int CF_SW2  = CF_SW1 + 108 * 24;       // [108][24] (m-major)
static constexpr int CF_SBN  = CF_SW2 + 108 * 24;       // [2][24]
static constexpr int CF_SMEM = (CF_SBN + 48) * 4;       // ~77 KB

__global__ __launch_bounds__(288, 2)
void cat_fused(const float* __restrict__ x, const float* __restrict__ w1,
               const float* __restrict__ bg, const float* __restrict__ bb,
               const float* __restrict__ bm, const float* __restrict__ bv,
               const float* __restrict__ w2, float* __restrict__ out) {
  extern __shared__ float sm[];
  float* sx  = sm + CF_SX;    // [kh][ic][iw+1], zero-padded
  float* sy  = sm + CF_SY;    // [oc][px]
  float* sw1 = sm + CF_SW1;   // [ic*9+tap][oc]
  float* sw2 = sm + CF_SW2;   // [mask][k], rows of 24 floats (16B aligned)
  float* sbn = sm + CF_SBN;

  const int tid = threadIdx.x;
  const int h = blockIdx.x, b = blockIdx.y;

  // stage weights
  for (int i = tid; i < 24 * 108; i += 288) {
    const int oc = i / 108, rem = i - oc * 108;   // rem = ic*9 + tap
    sw1[rem * 24 + oc] = w1[i];
  }
  for (int i = tid; i < 108 * 24; i += 288) sw2[i] = w2[i];
  if (tid < 24) {
    const float s = bg[tid] * rsqrtf(bv[tid] + 1e-5f);
    sbn[tid]      = s;
    sbn[24 + tid] = bb[tid] - bm[tid] * s;
  }
  // stage x rows 2h-1..2h+1, zero-padded
  for (int i = tid; i < 3 * 12 * 290; i += 288) {
    const int r  = i / (12 * 290);
    const int rem = i - r * (12 * 290);
    const int c  = rem / 290;
    const int iw = rem - c * 290 - 1;
    const int ih = 2 * h - 1 + r;
    float v = 0.f;
    if ((unsigned)ih < (unsigned)H && (unsigned)iw < (unsigned)W)
      v = x[((size_t)(b * 12 + c) * H + ih) * W + iw];
    sx[(r * 12 + c) * 292 + iw + 1] = v;
  }
  __syncthreads();

  const int px   = tid % 144;
  const int half = tid / 144;

  // conv: 12 output channels per thread
  {
    float acc[12];
#pragma unroll
    for (int o = 0; o < 12; ++o) acc[o] = 0.f;
#pragma unroll 3
    for (int ic = 0; ic < 12; ++ic) {
#pragma unroll
      for (int kh = 0; kh < 3; ++kh) {
#pragma unroll
        for (int kw = 0; kw < 3; ++kw) {
          const float xv = sx[(kh * 12 + ic) * 292 + 2 * px + kw];
          const float* wr = &sw1[(ic * 9 + kh * 3 + kw) * 24 + half * 12];
          const float4 wa = *(const float4*)(wr);
          const float4 wb = *(const float4*)(wr + 4);
          const float4 wc = *(const float4*)(wr + 8);
          acc[0] += xv * wa.x; acc[1] += xv * wa.y;
          acc[2] += xv * wa.z; acc[3] += xv * wa.w;
          acc[4] += xv * wb.x; acc[5] += xv * wb.y;
          acc[6] += xv * wb.z; acc[7] += xv * wb.w;
          acc[8] += xv * wc.x; acc[9] += xv * wc.y;
          acc[10] += xv * wc.z; acc[11] += xv * wc.w;
        }
      }
    }
#pragma unroll
    for (int o = 0; o < 12; ++o) {
      const int oc = half * 12 + o;
      float v = acc[o] * sbn[oc] + sbn[24 + oc];
      v = (v >= 0.f) ? v : 0.1f * v;
      sy[oc * 148 + px] = v;
    }
  }
  __syncthreads();

  // mask conv + softmax + combine, per group (thread owns 6 groups)
  float yv[24];
#pragma unroll
  for (int k = 0; k < 24; ++k) yv[k] = sy[k * 148 + px];

#pragma unroll 1
  for (int gl = 0; gl < 6; ++gl) {
    const int g = half * 6 + gl;
    float l9[9];
#pragma unroll
    for (int k9 = 0; k9 < 9; ++k9) {
      const float4* wv = (const float4*)&sw2[(g * 9 + k9) * 24];
      float a = 0.f;
#pragma unroll
      for (int q = 0; q < 6; ++q) {
        const float4 w4 = wv[q];
        a += yv[4 * q] * w4.x + yv[4 * q + 1] * w4.y +
             yv[4 * q + 2] * w4.z + yv[4 * q + 3] * w4.w;
      }
      l9[k9] = a;
    }
    float mx = l9[0];
#pragma unroll
    for (int k = 1; k < 9; ++k) mx = fmaxf(mx, l9[k]);
    float sum = 0.f;
#pragma unroll
    for (int k = 0; k < 9; ++k) { l9[k] = __expf(l9[k] - mx); sum += l9[k]; }
    const float inv = 1.f / sum;
    float s = 0.f;
#pragma unroll
    for (int kh = 0; kh < 3; ++kh)
#pragma unroll
      for (int kw = 0; kw < 3; ++kw)
        s += l9[kh * 3 + kw] * inv * sx[(kh * 12 + g) * 292 + 2 * px + kw];
    out[(size_t)(b * 12 + g) * NPIX + h * 144 + px] = s;
  }
}

// ---------------------------------------------------------------------------
// Cost volumes
// ---------------------------------------------------------------------------
__global__ void gwc_volume(const float* __restrict__ g8x, float* __restrict__ out) {
  __shared__ float lrow[12][WO];
  __shared__ float rrow[12][WO];
  const int h = blockIdx.x, g = blockIdx.y, b = blockIdx.z;
  for (int i = threadIdx.x; i < 12 * WO; i += 256) {
    int c = i / WO, w = i - c * WO;
    size_t base = ((size_t)(b * 96 + g * 12 + c) * HO + h) * WO + w;
    lrow[c][w] = g8x[base];
    rrow[c][w] = g8x[base + (size_t)2 * 96 * NPIX];
  }
  __syncthreads();
  for (int i = threadIdx.x; i < DMAX * WO; i += 256) {
    int d = i / WO, w = i - d * WO;
    float s = 0.f;
    if (w >= d) {
#pragma unroll
      for (int c = 0; c < 12; ++c) s += lrow[c][w] * rrow[c][w - d];
      s *= (1.f / 12.f);
    }
    out[(((size_t)(b * 32 + g) * DMAX + d) * HO + h) * WO + w] = s;
  }
}

__global__ void cat_volume(const float* __restrict__ c8x, float* __restrict__ out) {
  const int idx = blockIdx.x * 256 + threadIdx.x;
  int w = idx % WO;
  int t = idx / WO;
  int hh = t % HO;  t /= HO;
  int d  = t % DMAX; t /= DMAX;
  int c24 = t % 24;
  int b   = t / 24;
  float v = 0.f;
  if (w >= d) {
    if (c24 < 12)
      v = c8x[((size_t)(b * 12 + c24) * HO + hh) * WO + w];
    else
      v = c8x[((size_t)((b + 2) * 12 + (c24 - 12)) * HO + hh) * WO + (w - d)];
  }
  out[(((size_t)(b * 32 + 8 + c24) * DMAX + d) * HO + hh) * WO + w] = v;
}

// ---------------------------------------------------------------------------
// launch
// ---------------------------------------------------------------------------
extern "C" void kernel_launch(void* const* d_in, const int* in_sizes, int n_in,
                              void* d_out, int out_size) {
  const float* gwc_f = (const float*)d_in[0];
  const float* cat_f = (const float*)d_in[1];
  const float* gw1 = (const float*)d_in[2];
  const float* gbg = (const float*)d_in[3];
  const float* gbb = (const float*)d_in[4];
  const float* gbm = (const float*)d_in[5];
  const float* gbv = (const float*)d_in[6];
  const float* gw2 = (const float*)d_in[7];
  const float* cw1 = (const float*)d_in[8];
  const float* cbg = (const float*)d_in[9];
  const float* cbb = (const float*)d_in[10];
  const float* cbm = (const float*)d_in[11];
  const float* cbv = (const float*)d_in[12];
  const float* cw2 = (const float*)d_in[13];
  float* out = (float*)d_out;

  float *y_gwc, *g8x, *c8x;
  cudaGetSymbolAddress((void**)&y_gwc, g_y_gwc);
  cudaGetSymbolAddress((void**)&g8x,  g_g8x);
  cudaGetSymbolAddress((void**)&c8x,  g_c8x);

  cudaFuncSetAttribute(conv_mma, cudaFuncAttributeMaxDynamicSharedMemorySize,
                       CONV_SMEM);
  cudaFuncSetAttribute(mask_combine_mma,
                       cudaFuncAttributeMaxDynamicSharedMemorySize, MASK_SMEM);
  cudaFuncSetAttribute(cat_fused,
                       cudaFuncAttributeMaxDynamicSharedMemorySize, CF_SMEM);

  // weight prep (both sets, one launch)
  prep_all<<<(108 * 12 * 32 + 24 * 9 * 32 + 255) / 256, 256>>>(gw1, gw2);

  // gwc branch 96 -> 192 via TF32 mma.sync implicit GEMM
  conv_mma<<<dim3(9, 10, 12), 256, CONV_SMEM>>>(gwc_f, gbg, gbb, gbm, gbv, y_gwc);

  // cat branch fully fused (conv + bn + lrelu + mask + softmax + combine)
  cat_fused<<<dim3(80, 4), 288, CF_SMEM>>>(cat_f, cw1, cbg, cbb, cbm, cbv,
                                           cw2, c8x);

  // fused mask conv (mma) + softmax + adaptive combine, gwc branch
  mask_combine_mma<<<dim3(80, 4), 288, MASK_SMEM>>>(y_gwc, gwc_f, g8x);

  // cost volumes straight into d_out
  gwc_volume<<<dim3(HO, 8, 2), 256>>>(g8x, out);
  cat_volume<<<(2 * 24 * DMAX * NPIX) / 256, 256>>>(c8x, out);
}